// round 7
// baseline (speedup 1.0000x reference)
#include <cuda_runtime.h>
#include <cuda_bf16.h>
#include <cstdint>

// ---------------------------------------------------------------------------
// TotalAttention (Swin window attention), 3xBF16 pipeline:
//   0a) split_x: x fp32 -> xhi/xres bf16 planes
//   0b) pack_w: wq(*scale)|wkv -> transposed split planes; wp planes; biases;
//       bias table g_bias[h][n][m]
//   1) gemm_bf16x3 grid(6, 2048): qkv = x @ wqkv + bqkv -> fp32
//      (n-tile fastest => 6 blocks sharing an A m-tile run concurrently;
//       A re-reads served by L2)
//   2) attn (512 thr, 2 warps/head, 3xTF32) -> ao bf16 hi/res planes
//   3) gemm_bf16x3 grid(2, 2048): out = ao @ wp + bp -> d_out fp32
// ---------------------------------------------------------------------------

#define B_WIN   4096
#define N_TOK   64
#define DIM_C   256
#define HEADS   8
#define HDIM    32
#define M_ROWS  (B_WIN * N_TOK)        // 262144
#define QKV_LD  768
#define SCALE_F 0.17677669529663687f   // 32^-0.5

__device__ float g_qkv[(size_t)M_ROWS * QKV_LD];            // 805 MB fp32
__device__ unsigned short g_xhi  [(size_t)M_ROWS * DIM_C];
__device__ unsigned short g_xres [(size_t)M_ROWS * DIM_C];
__device__ unsigned short g_aohi [(size_t)M_ROWS * DIM_C];
__device__ unsigned short g_aores[(size_t)M_ROWS * DIM_C];
__device__ unsigned short g_wthi [QKV_LD * DIM_C];          // wqkv^T [768][256]
__device__ unsigned short g_wtres[QKV_LD * DIM_C];
__device__ unsigned short g_wpthi [DIM_C * DIM_C];          // wp^T [256][256]
__device__ unsigned short g_wptres[DIM_C * DIM_C];
__device__ float g_bqkv[QKV_LD];
__device__ float g_bias[HEADS * N_TOK * N_TOK];             // [h][n][m]

// ---------------------------------------------------------------------------
__device__ __forceinline__ void cp_async16(void* smem_dst, const void* gsrc) {
    unsigned saddr = (unsigned)__cvta_generic_to_shared(smem_dst);
    asm volatile("cp.async.cg.shared.global [%0], [%1], 16;\n"
                 :: "r"(saddr), "l"(gsrc));
}

__device__ __forceinline__ void mma_bf16(float* c, const unsigned* a, const unsigned* b) {
    asm volatile(
        "mma.sync.aligned.m16n8k16.row.col.f32.bf16.bf16.f32 "
        "{%0,%1,%2,%3}, {%4,%5,%6,%7}, {%8,%9}, {%0,%1,%2,%3};\n"
        : "+f"(c[0]), "+f"(c[1]), "+f"(c[2]), "+f"(c[3])
        : "r"(a[0]), "r"(a[1]), "r"(a[2]), "r"(a[3]),
          "r"(b[0]), "r"(b[1]));
}

__device__ __forceinline__ void mma_tf32(float* c, const unsigned* a, const unsigned* b) {
    asm volatile(
        "mma.sync.aligned.m16n8k8.row.col.f32.tf32.tf32.f32 "
        "{%0,%1,%2,%3}, {%4,%5,%6,%7}, {%8,%9}, {%0,%1,%2,%3};\n"
        : "+f"(c[0]), "+f"(c[1]), "+f"(c[2]), "+f"(c[3])
        : "r"(a[0]), "r"(a[1]), "r"(a[2]), "r"(a[3]),
          "r"(b[0]), "r"(b[1]));
}

__device__ __forceinline__ void tf32_split(float f, unsigned& hi, unsigned& res) {
    hi  = __float_as_uint(f) & 0xFFFFE000u;
    res = __float_as_uint(f - __uint_as_float(hi));
}

__device__ __forceinline__ void bf16_split(float f, unsigned short& hi, unsigned short& res) {
    __nv_bfloat16 h = __float2bfloat16_rn(f);
    float r = f - __bfloat162float(h);
    hi  = __bfloat16_as_ushort(h);
    res = __bfloat16_as_ushort(__float2bfloat16_rn(r));
}

__device__ __forceinline__ void bf16_split_pack(float a, float b, unsigned& hi, unsigned& res) {
    unsigned short ha, ra, hb, rb;
    bf16_split(a, ha, ra);
    bf16_split(b, hb, rb);
    hi  = (unsigned)ha | ((unsigned)hb << 16);
    res = (unsigned)ra | ((unsigned)rb << 16);
}

// ---------------------------------------------------------------------------
__global__ __launch_bounds__(256)
void split_x(const float* __restrict__ x)
{
    size_t idx = (size_t)blockIdx.x * blockDim.x + threadIdx.x;
    if (idx < (size_t)M_ROWS * DIM_C / 2) {
        float2 v = ((const float2*)x)[idx];
        unsigned hi, res;
        bf16_split_pack(v.x, v.y, hi, res);
        ((unsigned*)g_xhi)[idx]  = hi;
        ((unsigned*)g_xres)[idx] = res;
    }
}

// ---------------------------------------------------------------------------
__global__ void pack_w(const float* __restrict__ wq, const float* __restrict__ bq,
                       const float* __restrict__ wkv, const float* __restrict__ bkv,
                       const float* __restrict__ wp,
                       const float* __restrict__ rpb, const int* __restrict__ relidx)
{
    int i = blockIdx.x * blockDim.x + threadIdx.x;
    if (i < QKV_LD * DIM_C) {                 // wqkv^T: [n=768][k=256]
        int n = i / DIM_C, k = i % DIM_C;
        float v = (n < DIM_C) ? wq[k * DIM_C + n] * SCALE_F
                              : wkv[k * 512 + (n - DIM_C)];
        bf16_split(v, g_wthi[i], g_wtres[i]);
    }
    if (i < DIM_C * DIM_C) {                  // wp^T: [n=256][k=256]
        int n = i / DIM_C, k = i % DIM_C;
        bf16_split(wp[k * DIM_C + n], g_wpthi[i], g_wptres[i]);
    }
    if (i < QKV_LD) g_bqkv[i] = (i < DIM_C) ? bq[i] * SCALE_F : bkv[i - DIM_C];
    if (i < HEADS * N_TOK * N_TOK) {
        int h = i >> 12, nm = i & 4095;
        g_bias[i] = rpb[relidx[nm] * HEADS + h];
    }
}

// ---------------------------------------------------------------------------
// 3xBF16 pipelined GEMM: C[m,n] = A[m,:K] @ B[n,:K]^T + bias[n]
// A planes [M][K], B planes [N][K] bf16 hi/res. BM=BN=128, BK=32;
// 256 thr = 8 warps (2x4), warp tile 64x32; m16n8k16; double-buffered cp.async.
// grid = (N/128, M/128): n-tile fastest -> blocks sharing A run concurrently,
// A re-reads hit L2.
// ---------------------------------------------------------------------------
#define TPAD 40
#define TE (128 * TPAD)
#define BUF_ELEMS (4 * TE)
#define GEMM_SMEM (2 * BUF_ELEMS * 2)   // 81920 bytes

__global__ __launch_bounds__(256, 2)
void gemm_bf16x3(const unsigned short* __restrict__ Ahi,
                 const unsigned short* __restrict__ Ares,
                 const unsigned short* __restrict__ Bhi,
                 const unsigned short* __restrict__ Bres,
                 const float* __restrict__ bias, float* __restrict__ C,
                 int K, int ldc)
{
    extern __shared__ __align__(16) unsigned short smu[];

    const int tid  = threadIdx.x;
    const int warp = tid >> 5, lane = tid & 31;
    const int wm = warp >> 2, wn = warp & 3;
    const int g  = lane >> 2, t  = lane & 3;
    const size_t n0 = (size_t)blockIdx.x * 128;   // n fastest (L2 A-reuse)
    const size_t m0 = (size_t)blockIdx.y * 128;

    const int c0   = tid * 2;
    const int row0 = c0 >> 2, cc0 = (c0 & 3) * 8;
    const int row1 = (c0 + 1) >> 2, cc1 = ((c0 + 1) & 3) * 8;

    const int nkt = K / 32;

    float acc[4][4][4];
#pragma unroll
    for (int mt = 0; mt < 4; mt++)
#pragma unroll
        for (int nt = 0; nt < 4; nt++)
#pragma unroll
            for (int r = 0; r < 4; r++) acc[mt][nt][r] = 0.0f;

    {
        unsigned short* s = smu;
        cp_async16(&s[0 * TE + row0 * TPAD + cc0], Ahi  + (m0 + row0) * K + cc0);
        cp_async16(&s[0 * TE + row1 * TPAD + cc1], Ahi  + (m0 + row1) * K + cc1);
        cp_async16(&s[1 * TE + row0 * TPAD + cc0], Ares + (m0 + row0) * K + cc0);
        cp_async16(&s[1 * TE + row1 * TPAD + cc1], Ares + (m0 + row1) * K + cc1);
        cp_async16(&s[2 * TE + row0 * TPAD + cc0], Bhi  + (n0 + row0) * K + cc0);
        cp_async16(&s[2 * TE + row1 * TPAD + cc1], Bhi  + (n0 + row1) * K + cc1);
        cp_async16(&s[3 * TE + row0 * TPAD + cc0], Bres + (n0 + row0) * K + cc0);
        cp_async16(&s[3 * TE + row1 * TPAD + cc1], Bres + (n0 + row1) * K + cc1);
        asm volatile("cp.async.commit_group;\n");
    }

    for (int kt = 0; kt < nkt; ++kt) {
        asm volatile("cp.async.wait_group 0;\n");
        __syncthreads();

        if (kt + 1 < nkt) {
            unsigned short* s = smu + ((kt + 1) & 1) * BUF_ELEMS;
            const int ko = (kt + 1) * 32;
            cp_async16(&s[0 * TE + row0 * TPAD + cc0], Ahi  + (m0 + row0) * K + ko + cc0);
            cp_async16(&s[0 * TE + row1 * TPAD + cc1], Ahi  + (m0 + row1) * K + ko + cc1);
            cp_async16(&s[1 * TE + row0 * TPAD + cc0], Ares + (m0 + row0) * K + ko + cc0);
            cp_async16(&s[1 * TE + row1 * TPAD + cc1], Ares + (m0 + row1) * K + ko + cc1);
            cp_async16(&s[2 * TE + row0 * TPAD + cc0], Bhi  + (n0 + row0) * K + ko + cc0);
            cp_async16(&s[2 * TE + row1 * TPAD + cc1], Bhi  + (n0 + row1) * K + ko + cc1);
            cp_async16(&s[3 * TE + row0 * TPAD + cc0], Bres + (n0 + row0) * K + ko + cc0);
            cp_async16(&s[3 * TE + row1 * TPAD + cc1], Bres + (n0 + row1) * K + ko + cc1);
            asm volatile("cp.async.commit_group;\n");
        }

        const unsigned short* sb = smu + (kt & 1) * BUF_ELEMS;
        const unsigned short* As_hi  = sb + 0 * TE;
        const unsigned short* As_res = sb + 1 * TE;
        const unsigned short* Bs_hi  = sb + 2 * TE;
        const unsigned short* Bs_res = sb + 3 * TE;

#pragma unroll
        for (int ks = 0; ks < 2; ++ks) {
            const int ck = ks * 16;
            unsigned bh[4][2], br[4][2];
#pragma unroll
            for (int nt = 0; nt < 4; nt++) {
                const int np = wn * 32 + nt * 8 + g;
                const unsigned short* ph = Bs_hi  + np * TPAD + ck + 2 * t;
                const unsigned short* pr = Bs_res + np * TPAD + ck + 2 * t;
                bh[nt][0] = *(const unsigned*)ph;
                bh[nt][1] = *(const unsigned*)(ph + 8);
                br[nt][0] = *(const unsigned*)pr;
                br[nt][1] = *(const unsigned*)(pr + 8);
            }
#pragma unroll
            for (int mt = 0; mt < 4; mt++) {
                const int r0 = wm * 64 + mt * 16 + g;
                const unsigned short* ph = As_hi  + r0 * TPAD + ck + 2 * t;
                const unsigned short* pr = As_res + r0 * TPAD + ck + 2 * t;
                unsigned ah[4], ar[4];
                ah[0] = *(const unsigned*)ph;
                ah[1] = *(const unsigned*)(ph + 8 * TPAD);
                ah[2] = *(const unsigned*)(ph + 8);
                ah[3] = *(const unsigned*)(ph + 8 * TPAD + 8);
                ar[0] = *(const unsigned*)pr;
                ar[1] = *(const unsigned*)(pr + 8 * TPAD);
                ar[2] = *(const unsigned*)(pr + 8);
                ar[3] = *(const unsigned*)(pr + 8 * TPAD + 8);
#pragma unroll
                for (int nt = 0; nt < 4; nt++) {
                    mma_bf16(acc[mt][nt], ar, bh[nt]);
                    mma_bf16(acc[mt][nt], ah, br[nt]);
                    mma_bf16(acc[mt][nt], ah, bh[nt]);
                }
            }
        }
        __syncthreads();
    }

#pragma unroll
    for (int mt = 0; mt < 4; mt++) {
        const size_t r0 = m0 + wm * 64 + mt * 16 + g;
#pragma unroll
        for (int nt = 0; nt < 4; nt++) {
            const size_t col = n0 + wn * 32 + nt * 8 + 2 * t;
            const float b0 = bias[col], b1 = bias[col + 1];
            float* cp0 = C + r0 * ldc + col;
            float* cp1 = C + (r0 + 8) * ldc + col;
            *(float2*)cp0 = make_float2(acc[mt][nt][0] + b0, acc[mt][nt][1] + b1);
            *(float2*)cp1 = make_float2(acc[mt][nt][2] + b0, acc[mt][nt][3] + b1);
        }
    }
}

// ---------------------------------------------------------------------------
// Attention: block = window (512 threads), 2 warps per head (warp = 32 rows).
// Per-head smem: Q[64x32]@36 | K[64x32]@36 | V[64x32]@40 fp32; P@68 aliases Q+K.
// Pair sync via named barrier (1+h). 3xTF32 mma; softmax in registers.
// ---------------------------------------------------------------------------
#define QS_STRIDE 36
#define KS_STRIDE 36
#define VS_STRIDE 40
#define PS_STRIDE 68
#define HEAD_FLOATS (64 * QS_STRIDE + 64 * KS_STRIDE + 64 * VS_STRIDE)  // 7168
#define ATTN_SMEM (8 * HEAD_FLOATS * 4)   // 229376 bytes

__global__ __launch_bounds__(512, 1)
void attn_tc(const float* __restrict__ qkv,
             const float* __restrict__ bias)
{
    extern __shared__ float sm[];
    const int b    = blockIdx.x;
    const int warp = threadIdx.x >> 5;
    const int lane = threadIdx.x & 31;
    const int h    = warp >> 1;
    const int half = warp & 1;
    const int g = lane >> 2, t = lane & 3;

    float* QS = sm + h * HEAD_FLOATS;
    float* KS = QS + 64 * QS_STRIDE;
    float* VS = KS + 64 * KS_STRIDE;
    float* PS = QS;

    const size_t base = (size_t)b * N_TOK * QKV_LD + h * HDIM;
    for (int i = half * 32 + lane; i < 512; i += 64) {
        const int row = i >> 3;
        const int c4  = (i & 7) << 2;
        const float* rp = qkv + base + (size_t)row * QKV_LD + c4;
        float4 q = *(const float4*)(rp);
        float4 k = *(const float4*)(rp + 256);
        float4 v = *(const float4*)(rp + 512);
        *(float4*)&QS[row * QS_STRIDE + c4] = q;
        *(float4*)&KS[row * KS_STRIDE + c4] = k;
        *(float4*)&VS[row * VS_STRIDE + c4] = v;
    }
    __syncthreads();

    float s_[2][8][4];
#pragma unroll
    for (int mt = 0; mt < 2; mt++)
#pragma unroll
        for (int nt = 0; nt < 8; nt++)
#pragma unroll
            for (int r = 0; r < 4; r++) s_[mt][nt][r] = 0.0f;

#pragma unroll
    for (int ks = 0; ks < 4; ++ks) {
        const int ck = ks * 8;
        unsigned ah[2][4], ar[2][4];
#pragma unroll
        for (int mt = 0; mt < 2; mt++) {
            const float* p = QS + (half * 32 + mt * 16 + g) * QS_STRIDE + ck + t;
            tf32_split(p[0],                 ah[mt][0], ar[mt][0]);
            tf32_split(p[8 * QS_STRIDE],     ah[mt][1], ar[mt][1]);
            tf32_split(p[4],                 ah[mt][2], ar[mt][2]);
            tf32_split(p[8 * QS_STRIDE + 4], ah[mt][3], ar[mt][3]);
        }
#pragma unroll
        for (int nt = 0; nt < 8; nt++) {
            const float* p = KS + (nt * 8 + g) * KS_STRIDE + ck + t;
            unsigned bh[2], br[2];
            tf32_split(p[0], bh[0], br[0]);
            tf32_split(p[4], bh[1], br[1]);
#pragma unroll
            for (int mt = 0; mt < 2; mt++) {
                mma_tf32(s_[mt][nt], ar[mt], bh);
                mma_tf32(s_[mt][nt], ah[mt], br);
                mma_tf32(s_[mt][nt], ah[mt], bh);
            }
        }
    }

    const float* bh_tab = bias + h * (N_TOK * N_TOK);
#pragma unroll
    for (int mt = 0; mt < 2; mt++) {
        const int r0 = half * 32 + mt * 16 + g;
#pragma unroll
        for (int nt = 0; nt < 8; nt++) {
            const int c = nt * 8 + 2 * t;
            float2 b0 = *(const float2*)&bh_tab[r0 * 64 + c];
            float2 b1 = *(const float2*)&bh_tab[(r0 + 8) * 64 + c];
            s_[mt][nt][0] += b0.x;  s_[mt][nt][1] += b0.y;
            s_[mt][nt][2] += b1.x;  s_[mt][nt][3] += b1.y;
        }
    }

#pragma unroll
    for (int mt = 0; mt < 2; mt++) {
        float m0 = -1e30f, m1 = -1e30f;
#pragma unroll
        for (int nt = 0; nt < 8; nt++) {
            m0 = fmaxf(m0, fmaxf(s_[mt][nt][0], s_[mt][nt][1]));
            m1 = fmaxf(m1, fmaxf(s_[mt][nt][2], s_[mt][nt][3]));
        }
        m0 = fmaxf(m0, __shfl_xor_sync(0xffffffffu, m0, 1));
        m0 = fmaxf(m0, __shfl_xor_sync(0xffffffffu, m0, 2));
        m1 = fmaxf(m1, __shfl_xor_sync(0xffffffffu, m1, 1));
        m1 = fmaxf(m1, __shfl_xor_sync(0xffffffffu, m1, 2));
        float s0 = 0.0f, s1 = 0.0f;
#pragma unroll
        for (int nt = 0; nt < 8; nt++) {
            s_[mt][nt][0] = __expf(s_[mt][nt][0] - m0);
            s_[mt][nt][1] = __expf(s_[mt][nt][1] - m0);
            s_[mt][nt][2] = __expf(s_[mt][nt][2] - m1);
            s_[mt][nt][3] = __expf(s_[mt][nt][3] - m1);
            s0 += s_[mt][nt][0] + s_[mt][nt][1];
            s1 += s_[mt][nt][2] + s_[mt][nt][3];
        }
        s0 += __shfl_xor_sync(0xffffffffu, s0, 1);
        s0 += __shfl_xor_sync(0xffffffffu, s0, 2);
        s1 += __shfl_xor_sync(0xffffffffu, s1, 1);
        s1 += __shfl_xor_sync(0xffffffffu, s1, 2);
        const float i0 = __frcp_rn(s0), i1 = __frcp_rn(s1);
#pragma unroll
        for (int nt = 0; nt < 8; nt++) {
            s_[mt][nt][0] *= i0;  s_[mt][nt][1] *= i0;
            s_[mt][nt][2] *= i1;  s_[mt][nt][3] *= i1;
        }
    }

    asm volatile("bar.sync %0, %1;" :: "r"(1 + h), "r"(64) : "memory");

#pragma unroll
    for (int mt = 0; mt < 2; mt++) {
        const int r0 = half * 32 + mt * 16 + g;
#pragma unroll
        for (int nt = 0; nt < 8; nt++) {
            const int c = nt * 8 + 2 * t;
            *(float2*)&PS[r0 * PS_STRIDE + c]       = make_float2(s_[mt][nt][0], s_[mt][nt][1]);
            *(float2*)&PS[(r0 + 8) * PS_STRIDE + c] = make_float2(s_[mt][nt][2], s_[mt][nt][3]);
        }
    }
    asm volatile("bar.sync %0, %1;" :: "r"(1 + h), "r"(64) : "memory");

    float o[2][4][4];
#pragma unroll
    for (int mt = 0; mt < 2; mt++)
#pragma unroll
        for (int nt = 0; nt < 4; nt++)
#pragma unroll
            for (int r = 0; r < 4; r++) o[mt][nt][r] = 0.0f;

#pragma unroll
    for (int ks = 0; ks < 8; ++ks) {
        const int ck = ks * 8;
        unsigned ah[2][4], ar[2][4];
#pragma unroll
        for (int mt = 0; mt < 2; mt++) {
            const float* p = PS + (half * 32 + mt * 16 + g) * PS_STRIDE + ck + t;
            tf32_split(p[0],                 ah[mt][0], ar[mt][0]);
            tf32_split(p[8 * PS_STRIDE],     ah[mt][1], ar[mt][1]);
            tf32_split(p[4],                 ah[mt][2], ar[mt][2]);
            tf32_split(p[8 * PS_STRIDE + 4], ah[mt][3], ar[mt][3]);
        }
#pragma unroll
        for (int nt = 0; nt < 4; nt++) {
            const float* p = VS + (ck + t) * VS_STRIDE + nt * 8 + g;
            unsigned bh[2], br[2];
            tf32_split(p[0],             bh[0], br[0]);
            tf32_split(p[4 * VS_STRIDE], bh[1], br[1]);
#pragma unroll
            for (int mt = 0; mt < 2; mt++) {
                mma_tf32(o[mt][nt], ar[mt], bh);
                mma_tf32(o[mt][nt], ah[mt], br);
                mma_tf32(o[mt][nt], ah[mt], bh);
            }
        }
    }

#pragma unroll
    for (int mt = 0; mt < 2; mt++) {
        const int r0 = half * 32 + mt * 16 + g;
#pragma unroll
        for (int nt = 0; nt < 4; nt++) {
            const int col = h * HDIM + nt * 8 + 2 * t;
            const size_t e0 = ((size_t)b * N_TOK + r0)     * DIM_C + col;
            const size_t e1 = ((size_t)b * N_TOK + r0 + 8) * DIM_C + col;
            unsigned hi, res;
            bf16_split_pack(o[mt][nt][0], o[mt][nt][1], hi, res);
            ((unsigned*)g_aohi)[e0 >> 1]  = hi;
            ((unsigned*)g_aores)[e0 >> 1] = res;
            bf16_split_pack(o[mt][nt][2], o[mt][nt][3], hi, res);
            ((unsigned*)g_aohi)[e1 >> 1]  = hi;
            ((unsigned*)g_aores)[e1 >> 1] = res;
        }
    }
}

// ---------------------------------------------------------------------------
extern "C" void kernel_launch(void* const* d_in, const int* in_sizes, int n_in,
                              void* d_out, int out_size)
{
    const float* x      = (const float*)d_in[0];
    const float* wq     = (const float*)d_in[1];
    const float* bq     = (const float*)d_in[2];
    const float* wkv    = (const float*)d_in[3];
    const float* bkv    = (const float*)d_in[4];
    const float* wp     = (const float*)d_in[5];
    const float* bp     = (const float*)d_in[6];
    const float* rpb    = (const float*)d_in[7];
    const int*   relidx = (const int*)  d_in[8];
    float* out = (float*)d_out;

    float *qkv = nullptr, *bqkv = nullptr, *bias = nullptr;
    unsigned short *xhi, *xres, *aohi, *aores, *wthi, *wtres, *wpthi, *wptres;
    cudaGetSymbolAddress((void**)&qkv,    g_qkv);
    cudaGetSymbolAddress((void**)&bqkv,   g_bqkv);
    cudaGetSymbolAddress((void**)&bias,   g_bias);
    cudaGetSymbolAddress((void**)&xhi,    g_xhi);
    cudaGetSymbolAddress((void**)&xres,   g_xres);
    cudaGetSymbolAddress((void**)&aohi,   g_aohi);
    cudaGetSymbolAddress((void**)&aores,  g_aores);
    cudaGetSymbolAddress((void**)&wthi,   g_wthi);
    cudaGetSymbolAddress((void**)&wtres,  g_wtres);
    cudaGetSymbolAddress((void**)&wpthi,  g_wpthi);
    cudaGetSymbolAddress((void**)&wptres, g_wptres);

    cudaFuncSetAttribute(gemm_bf16x3, cudaFuncAttributeMaxDynamicSharedMemorySize, GEMM_SMEM);
    cudaFuncSetAttribute(attn_tc,     cudaFuncAttributeMaxDynamicSharedMemorySize, ATTN_SMEM);

    // 0a) split x into bf16 hi/res planes
    split_x<<<(M_ROWS * DIM_C / 2 + 255) / 256, 256>>>(x);
    // 0b) pack weights (q pre-scaled) + bias table
    pack_w<<<(QKV_LD * DIM_C + 255) / 256, 256>>>(wq, bq, wkv, bkv, wp, rpb, relidx);

    // 1) qkv = x @ wqkv + bqkv  — n-tile fastest for L2 A-reuse
    {
        dim3 grid(QKV_LD / 128, M_ROWS / 128);   // (6, 2048)
        gemm_bf16x3<<<grid, 256, GEMM_SMEM>>>(xhi, xres, wthi, wtres, bqkv, qkv,
                                              DIM_C, QKV_LD);
    }
    // 2) attention
    attn_tc<<<B_WIN, 512, ATTN_SMEM>>>(qkv, bias);

    // 3) out = ao @ wp + bp
    {
        dim3 grid(DIM_C / 128, M_ROWS / 128);    // (2, 2048)
        gemm_bf16x3<<<grid, 256, GEMM_SMEM>>>(aohi, aores, wpthi, wptres, bp, out,
                                              DIM_C, DIM_C);
    }
}

// round 8
// speedup vs baseline: 1.0307x; 1.0307x over previous
#include <cuda_runtime.h>
#include <cuda_bf16.h>
#include <cstdint>

// ---------------------------------------------------------------------------
// TotalAttention (Swin window attention), 3xBF16 pipeline, ldmatrix frags:
//   0a) split_x: x fp32 -> xhi/xres bf16 planes
//   0b) pack_w: wq(*scale)|wkv -> transposed split planes; wp planes; biases;
//       bias table g_bias[h][n][m]
//   1) gemm_bf16x3 grid(6, 2048): qkv = x @ wqkv + bqkv -> fp32
//   2) attn (512 thr, 2 warps/head, 3xTF32) -> ao bf16 hi/res planes
//   3) gemm_bf16x3 grid(2, 2048): out = ao @ wp + bp -> d_out fp32
// GEMM fragment loads now use ldmatrix (LDSM.x4 A / LDSM.x2 B): 16 LDSM per
// k16-step instead of 48 scalar LDS.
// ---------------------------------------------------------------------------

#define B_WIN   4096
#define N_TOK   64
#define DIM_C   256
#define HEADS   8
#define HDIM    32
#define M_ROWS  (B_WIN * N_TOK)        // 262144
#define QKV_LD  768
#define SCALE_F 0.17677669529663687f   // 32^-0.5

__device__ float g_qkv[(size_t)M_ROWS * QKV_LD];            // 805 MB fp32
__device__ unsigned short g_xhi  [(size_t)M_ROWS * DIM_C];
__device__ unsigned short g_xres [(size_t)M_ROWS * DIM_C];
__device__ unsigned short g_aohi [(size_t)M_ROWS * DIM_C];
__device__ unsigned short g_aores[(size_t)M_ROWS * DIM_C];
__device__ unsigned short g_wthi [QKV_LD * DIM_C];          // wqkv^T [768][256]
__device__ unsigned short g_wtres[QKV_LD * DIM_C];
__device__ unsigned short g_wpthi [DIM_C * DIM_C];          // wp^T [256][256]
__device__ unsigned short g_wptres[DIM_C * DIM_C];
__device__ float g_bqkv[QKV_LD];
__device__ float g_bias[HEADS * N_TOK * N_TOK];             // [h][n][m]

// ---------------------------------------------------------------------------
__device__ __forceinline__ void cp_async16(void* smem_dst, const void* gsrc) {
    unsigned saddr = (unsigned)__cvta_generic_to_shared(smem_dst);
    asm volatile("cp.async.cg.shared.global [%0], [%1], 16;\n"
                 :: "r"(saddr), "l"(gsrc));
}

__device__ __forceinline__ void ldsm_x4(unsigned* r, const void* p) {
    unsigned a = (unsigned)__cvta_generic_to_shared(p);
    asm volatile("ldmatrix.sync.aligned.m8n8.x4.shared.b16 {%0,%1,%2,%3}, [%4];"
                 : "=r"(r[0]), "=r"(r[1]), "=r"(r[2]), "=r"(r[3]) : "r"(a));
}

__device__ __forceinline__ void ldsm_x2(unsigned* r, const void* p) {
    unsigned a = (unsigned)__cvta_generic_to_shared(p);
    asm volatile("ldmatrix.sync.aligned.m8n8.x2.shared.b16 {%0,%1}, [%2];"
                 : "=r"(r[0]), "=r"(r[1]) : "r"(a));
}

__device__ __forceinline__ void mma_bf16(float* c, const unsigned* a, const unsigned* b) {
    asm volatile(
        "mma.sync.aligned.m16n8k16.row.col.f32.bf16.bf16.f32 "
        "{%0,%1,%2,%3}, {%4,%5,%6,%7}, {%8,%9}, {%0,%1,%2,%3};\n"
        : "+f"(c[0]), "+f"(c[1]), "+f"(c[2]), "+f"(c[3])
        : "r"(a[0]), "r"(a[1]), "r"(a[2]), "r"(a[3]),
          "r"(b[0]), "r"(b[1]));
}

__device__ __forceinline__ void mma_tf32(float* c, const unsigned* a, const unsigned* b) {
    asm volatile(
        "mma.sync.aligned.m16n8k8.row.col.f32.tf32.tf32.f32 "
        "{%0,%1,%2,%3}, {%4,%5,%6,%7}, {%8,%9}, {%0,%1,%2,%3};\n"
        : "+f"(c[0]), "+f"(c[1]), "+f"(c[2]), "+f"(c[3])
        : "r"(a[0]), "r"(a[1]), "r"(a[2]), "r"(a[3]),
          "r"(b[0]), "r"(b[1]));
}

__device__ __forceinline__ void tf32_split(float f, unsigned& hi, unsigned& res) {
    hi  = __float_as_uint(f) & 0xFFFFE000u;
    res = __float_as_uint(f - __uint_as_float(hi));
}

__device__ __forceinline__ void bf16_split(float f, unsigned short& hi, unsigned short& res) {
    __nv_bfloat16 h = __float2bfloat16_rn(f);
    float r = f - __bfloat162float(h);
    hi  = __bfloat16_as_ushort(h);
    res = __bfloat16_as_ushort(__float2bfloat16_rn(r));
}

__device__ __forceinline__ void bf16_split_pack(float a, float b, unsigned& hi, unsigned& res) {
    unsigned short ha, ra, hb, rb;
    bf16_split(a, ha, ra);
    bf16_split(b, hb, rb);
    hi  = (unsigned)ha | ((unsigned)hb << 16);
    res = (unsigned)ra | ((unsigned)rb << 16);
}

// ---------------------------------------------------------------------------
__global__ __launch_bounds__(256)
void split_x(const float* __restrict__ x)
{
    size_t idx = (size_t)blockIdx.x * blockDim.x + threadIdx.x;
    if (idx < (size_t)M_ROWS * DIM_C / 2) {
        float2 v = ((const float2*)x)[idx];
        unsigned hi, res;
        bf16_split_pack(v.x, v.y, hi, res);
        ((unsigned*)g_xhi)[idx]  = hi;
        ((unsigned*)g_xres)[idx] = res;
    }
}

// ---------------------------------------------------------------------------
__global__ void pack_w(const float* __restrict__ wq, const float* __restrict__ bq,
                       const float* __restrict__ wkv, const float* __restrict__ bkv,
                       const float* __restrict__ wp,
                       const float* __restrict__ rpb, const int* __restrict__ relidx)
{
    int i = blockIdx.x * blockDim.x + threadIdx.x;
    if (i < QKV_LD * DIM_C) {                 // wqkv^T: [n=768][k=256]
        int n = i / DIM_C, k = i % DIM_C;
        float v = (n < DIM_C) ? wq[k * DIM_C + n] * SCALE_F
                              : wkv[k * 512 + (n - DIM_C)];
        bf16_split(v, g_wthi[i], g_wtres[i]);
    }
    if (i < DIM_C * DIM_C) {                  // wp^T: [n=256][k=256]
        int n = i / DIM_C, k = i % DIM_C;
        bf16_split(wp[k * DIM_C + n], g_wpthi[i], g_wptres[i]);
    }
    if (i < QKV_LD) g_bqkv[i] = (i < DIM_C) ? bq[i] * SCALE_F : bkv[i - DIM_C];
    if (i < HEADS * N_TOK * N_TOK) {
        int h = i >> 12, nm = i & 4095;
        g_bias[i] = rpb[relidx[nm] * HEADS + h];
    }
}

// ---------------------------------------------------------------------------
// 3xBF16 pipelined GEMM with ldmatrix fragment loads.
// A planes [M][K], B planes [N][K] bf16 hi/res. BM=BN=128, BK=32;
// 256 thr = 8 warps (2x4), warp tile 64x32; m16n8k16; double-buffered cp.async.
// grid = (N/128, M/128): n-tile fastest -> L2 A-reuse.
// ldmatrix address mapping (stride 40 shorts = 80B, 16B-aligned rows):
//   A x4: row = m0 + (lane&15), col = ck + (lane>>4)*8  -> regs = a0..a3
//   B x2: row = n0 + (lane&7),  col = ck + ((lane>>3)&1)*8 -> regs = b0,b1
// ---------------------------------------------------------------------------
#define TPAD 40
#define TE (128 * TPAD)
#define BUF_ELEMS (4 * TE)
#define GEMM_SMEM (2 * BUF_ELEMS * 2)   // 81920 bytes

__global__ __launch_bounds__(256, 2)
void gemm_bf16x3(const unsigned short* __restrict__ Ahi,
                 const unsigned short* __restrict__ Ares,
                 const unsigned short* __restrict__ Bhi,
                 const unsigned short* __restrict__ Bres,
                 const float* __restrict__ bias, float* __restrict__ C,
                 int K, int ldc)
{
    extern __shared__ __align__(16) unsigned short smu[];

    const int tid  = threadIdx.x;
    const int warp = tid >> 5, lane = tid & 31;
    const int wm = warp >> 2, wn = warp & 3;
    const int g  = lane >> 2, t  = lane & 3;
    const size_t n0 = (size_t)blockIdx.x * 128;   // n fastest (L2 A-reuse)
    const size_t m0 = (size_t)blockIdx.y * 128;

    // cp.async staging mapping
    const int c0   = tid * 2;
    const int row0 = c0 >> 2, cc0 = (c0 & 3) * 8;
    const int row1 = (c0 + 1) >> 2, cc1 = ((c0 + 1) & 3) * 8;

    // ldmatrix lane mapping
    const int la_row = lane & 15;            // A row within 16
    const int la_col = (lane >> 4) * 8;      // A col offset (0 or 8)
    const int lb_row = lane & 7;             // B row within 8
    const int lb_col = ((lane >> 3) & 1) * 8;

    const int nkt = K / 32;

    float acc[4][4][4];
#pragma unroll
    for (int mt = 0; mt < 4; mt++)
#pragma unroll
        for (int nt = 0; nt < 4; nt++)
#pragma unroll
            for (int r = 0; r < 4; r++) acc[mt][nt][r] = 0.0f;

    {
        unsigned short* s = smu;
        cp_async16(&s[0 * TE + row0 * TPAD + cc0], Ahi  + (m0 + row0) * K + cc0);
        cp_async16(&s[0 * TE + row1 * TPAD + cc1], Ahi  + (m0 + row1) * K + cc1);
        cp_async16(&s[1 * TE + row0 * TPAD + cc0], Ares + (m0 + row0) * K + cc0);
        cp_async16(&s[1 * TE + row1 * TPAD + cc1], Ares + (m0 + row1) * K + cc1);
        cp_async16(&s[2 * TE + row0 * TPAD + cc0], Bhi  + (n0 + row0) * K + cc0);
        cp_async16(&s[2 * TE + row1 * TPAD + cc1], Bhi  + (n0 + row1) * K + cc1);
        cp_async16(&s[3 * TE + row0 * TPAD + cc0], Bres + (n0 + row0) * K + cc0);
        cp_async16(&s[3 * TE + row1 * TPAD + cc1], Bres + (n0 + row1) * K + cc1);
        asm volatile("cp.async.commit_group;\n");
    }

    for (int kt = 0; kt < nkt; ++kt) {
        asm volatile("cp.async.wait_group 0;\n");
        __syncthreads();

        if (kt + 1 < nkt) {
            unsigned short* s = smu + ((kt + 1) & 1) * BUF_ELEMS;
            const int ko = (kt + 1) * 32;
            cp_async16(&s[0 * TE + row0 * TPAD + cc0], Ahi  + (m0 + row0) * K + ko + cc0);
            cp_async16(&s[0 * TE + row1 * TPAD + cc1], Ahi  + (m0 + row1) * K + ko + cc1);
            cp_async16(&s[1 * TE + row0 * TPAD + cc0], Ares + (m0 + row0) * K + ko + cc0);
            cp_async16(&s[1 * TE + row1 * TPAD + cc1], Ares + (m0 + row1) * K + ko + cc1);
            cp_async16(&s[2 * TE + row0 * TPAD + cc0], Bhi  + (n0 + row0) * K + ko + cc0);
            cp_async16(&s[2 * TE + row1 * TPAD + cc1], Bhi  + (n0 + row1) * K + ko + cc1);
            cp_async16(&s[3 * TE + row0 * TPAD + cc0], Bres + (n0 + row0) * K + ko + cc0);
            cp_async16(&s[3 * TE + row1 * TPAD + cc1], Bres + (n0 + row1) * K + ko + cc1);
            asm volatile("cp.async.commit_group;\n");
        }

        const unsigned short* sb = smu + (kt & 1) * BUF_ELEMS;
        const unsigned short* As_hi  = sb + 0 * TE;
        const unsigned short* As_res = sb + 1 * TE;
        const unsigned short* Bs_hi  = sb + 2 * TE;
        const unsigned short* Bs_res = sb + 3 * TE;

#pragma unroll
        for (int ks = 0; ks < 2; ++ks) {
            const int ck = ks * 16;
            unsigned bh[4][2], br[4][2];
#pragma unroll
            for (int nt = 0; nt < 4; nt++) {
                const int boff = (wn * 32 + nt * 8 + lb_row) * TPAD + ck + lb_col;
                ldsm_x2(bh[nt], Bs_hi  + boff);
                ldsm_x2(br[nt], Bs_res + boff);
            }
#pragma unroll
            for (int mt = 0; mt < 4; mt++) {
                const int aoff = (wm * 64 + mt * 16 + la_row) * TPAD + ck + la_col;
                unsigned ah[4], ar[4];
                ldsm_x4(ah, As_hi  + aoff);
                ldsm_x4(ar, As_res + aoff);
#pragma unroll
                for (int nt = 0; nt < 4; nt++) {
                    mma_bf16(acc[mt][nt], ar, bh[nt]);
                    mma_bf16(acc[mt][nt], ah, br[nt]);
                    mma_bf16(acc[mt][nt], ah, bh[nt]);
                }
            }
        }
        __syncthreads();
    }

#pragma unroll
    for (int mt = 0; mt < 4; mt++) {
        const size_t r0 = m0 + wm * 64 + mt * 16 + g;
#pragma unroll
        for (int nt = 0; nt < 4; nt++) {
            const size_t col = n0 + wn * 32 + nt * 8 + 2 * t;
            const float b0 = bias[col], b1 = bias[col + 1];
            float* cp0 = C + r0 * ldc + col;
            float* cp1 = C + (r0 + 8) * ldc + col;
            *(float2*)cp0 = make_float2(acc[mt][nt][0] + b0, acc[mt][nt][1] + b1);
            *(float2*)cp1 = make_float2(acc[mt][nt][2] + b0, acc[mt][nt][3] + b1);
        }
    }
}

// ---------------------------------------------------------------------------
// Attention: block = window (512 threads), 2 warps per head (warp = 32 rows).
// Per-head smem: Q[64x32]@36 | K[64x32]@36 | V[64x32]@40 fp32; P@68 aliases Q+K.
// Pair sync via named barrier (1+h). 3xTF32 mma; softmax in registers.
// ---------------------------------------------------------------------------
#define QS_STRIDE 36
#define KS_STRIDE 36
#define VS_STRIDE 40
#define PS_STRIDE 68
#define HEAD_FLOATS (64 * QS_STRIDE + 64 * KS_STRIDE + 64 * VS_STRIDE)  // 7168
#define ATTN_SMEM (8 * HEAD_FLOATS * 4)   // 229376 bytes

__global__ __launch_bounds__(512, 1)
void attn_tc(const float* __restrict__ qkv,
             const float* __restrict__ bias)
{
    extern __shared__ float sm[];
    const int b    = blockIdx.x;
    const int warp = threadIdx.x >> 5;
    const int lane = threadIdx.x & 31;
    const int h    = warp >> 1;
    const int half = warp & 1;
    const int g = lane >> 2, t = lane & 3;

    float* QS = sm + h * HEAD_FLOATS;
    float* KS = QS + 64 * QS_STRIDE;
    float* VS = KS + 64 * KS_STRIDE;
    float* PS = QS;

    const size_t base = (size_t)b * N_TOK * QKV_LD + h * HDIM;
    for (int i = half * 32 + lane; i < 512; i += 64) {
        const int row = i >> 3;
        const int c4  = (i & 7) << 2;
        const float* rp = qkv + base + (size_t)row * QKV_LD + c4;
        float4 q = *(const float4*)(rp);
        float4 k = *(const float4*)(rp + 256);
        float4 v = *(const float4*)(rp + 512);
        *(float4*)&QS[row * QS_STRIDE + c4] = q;
        *(float4*)&KS[row * KS_STRIDE + c4] = k;
        *(float4*)&VS[row * VS_STRIDE + c4] = v;
    }
    __syncthreads();

    float s_[2][8][4];
#pragma unroll
    for (int mt = 0; mt < 2; mt++)
#pragma unroll
        for (int nt = 0; nt < 8; nt++)
#pragma unroll
            for (int r = 0; r < 4; r++) s_[mt][nt][r] = 0.0f;

#pragma unroll
    for (int ks = 0; ks < 4; ++ks) {
        const int ck = ks * 8;
        unsigned ah[2][4], ar[2][4];
#pragma unroll
        for (int mt = 0; mt < 2; mt++) {
            const float* p = QS + (half * 32 + mt * 16 + g) * QS_STRIDE + ck + t;
            tf32_split(p[0],                 ah[mt][0], ar[mt][0]);
            tf32_split(p[8 * QS_STRIDE],     ah[mt][1], ar[mt][1]);
            tf32_split(p[4],                 ah[mt][2], ar[mt][2]);
            tf32_split(p[8 * QS_STRIDE + 4], ah[mt][3], ar[mt][3]);
        }
#pragma unroll
        for (int nt = 0; nt < 8; nt++) {
            const float* p = KS + (nt * 8 + g) * KS_STRIDE + ck + t;
            unsigned bh[2], br[2];
            tf32_split(p[0], bh[0], br[0]);
            tf32_split(p[4], bh[1], br[1]);
#pragma unroll
            for (int mt = 0; mt < 2; mt++) {
                mma_tf32(s_[mt][nt], ar[mt], bh);
                mma_tf32(s_[mt][nt], ah[mt], br);
                mma_tf32(s_[mt][nt], ah[mt], bh);
            }
        }
    }

    const float* bh_tab = bias + h * (N_TOK * N_TOK);
#pragma unroll
    for (int mt = 0; mt < 2; mt++) {
        const int r0 = half * 32 + mt * 16 + g;
#pragma unroll
        for (int nt = 0; nt < 8; nt++) {
            const int c = nt * 8 + 2 * t;
            float2 b0 = *(const float2*)&bh_tab[r0 * 64 + c];
            float2 b1 = *(const float2*)&bh_tab[(r0 + 8) * 64 + c];
            s_[mt][nt][0] += b0.x;  s_[mt][nt][1] += b0.y;
            s_[mt][nt][2] += b1.x;  s_[mt][nt][3] += b1.y;
        }
    }

#pragma unroll
    for (int mt = 0; mt < 2; mt++) {
        float m0 = -1e30f, m1 = -1e30f;
#pragma unroll
        for (int nt = 0; nt < 8; nt++) {
            m0 = fmaxf(m0, fmaxf(s_[mt][nt][0], s_[mt][nt][1]));
            m1 = fmaxf(m1, fmaxf(s_[mt][nt][2], s_[mt][nt][3]));
        }
        m0 = fmaxf(m0, __shfl_xor_sync(0xffffffffu, m0, 1));
        m0 = fmaxf(m0, __shfl_xor_sync(0xffffffffu, m0, 2));
        m1 = fmaxf(m1, __shfl_xor_sync(0xffffffffu, m1, 1));
        m1 = fmaxf(m1, __shfl_xor_sync(0xffffffffu, m1, 2));
        float s0 = 0.0f, s1 = 0.0f;
#pragma unroll
        for (int nt = 0; nt < 8; nt++) {
            s_[mt][nt][0] = __expf(s_[mt][nt][0] - m0);
            s_[mt][nt][1] = __expf(s_[mt][nt][1] - m0);
            s_[mt][nt][2] = __expf(s_[mt][nt][2] - m1);
            s_[mt][nt][3] = __expf(s_[mt][nt][3] - m1);
            s0 += s_[mt][nt][0] + s_[mt][nt][1];
            s1 += s_[mt][nt][2] + s_[mt][nt][3];
        }
        s0 += __shfl_xor_sync(0xffffffffu, s0, 1);
        s0 += __shfl_xor_sync(0xffffffffu, s0, 2);
        s1 += __shfl_xor_sync(0xffffffffu, s1, 1);
        s1 += __shfl_xor_sync(0xffffffffu, s1, 2);
        const float i0 = __frcp_rn(s0), i1 = __frcp_rn(s1);
#pragma unroll
        for (int nt = 0; nt < 8; nt++) {
            s_[mt][nt][0] *= i0;  s_[mt][nt][1] *= i0;
            s_[mt][nt][2] *= i1;  s_[mt][nt][3] *= i1;
        }
    }

    asm volatile("bar.sync %0, %1;" :: "r"(1 + h), "r"(64) : "memory");

#pragma unroll
    for (int mt = 0; mt < 2; mt++) {
        const int r0 = half * 32 + mt * 16 + g;
#pragma unroll
        for (int nt = 0; nt < 8; nt++) {
            const int c = nt * 8 + 2 * t;
            *(float2*)&PS[r0 * PS_STRIDE + c]       = make_float2(s_[mt][nt][0], s_[mt][nt][1]);
            *(float2*)&PS[(r0 + 8) * PS_STRIDE + c] = make_float2(s_[mt][nt][2], s_[mt][nt][3]);
        }
    }
    asm volatile("bar.sync %0, %1;" :: "r"(1 + h), "r"(64) : "memory");

    float o[2][4][4];
#pragma unroll
    for (int mt = 0; mt < 2; mt++)
#pragma unroll
        for (int nt = 0; nt < 4; nt++)
#pragma unroll
            for (int r = 0; r < 4; r++) o[mt][nt][r] = 0.0f;

#pragma unroll
    for (int ks = 0; ks < 8; ++ks) {
        const int ck = ks * 8;
        unsigned ah[2][4], ar[2][4];
#pragma unroll
        for (int mt = 0; mt < 2; mt++) {
            const float* p = PS + (half * 32 + mt * 16 + g) * PS_STRIDE + ck + t;
            tf32_split(p[0],                 ah[mt][0], ar[mt][0]);
            tf32_split(p[8 * PS_STRIDE],     ah[mt][1], ar[mt][1]);
            tf32_split(p[4],                 ah[mt][2], ar[mt][2]);
            tf32_split(p[8 * PS_STRIDE + 4], ah[mt][3], ar[mt][3]);
        }
#pragma unroll
        for (int nt = 0; nt < 4; nt++) {
            const float* p = VS + (ck + t) * VS_STRIDE + nt * 8 + g;
            unsigned bh[2], br[2];
            tf32_split(p[0],             bh[0], br[0]);
            tf32_split(p[4 * VS_STRIDE], bh[1], br[1]);
#pragma unroll
            for (int mt = 0; mt < 2; mt++) {
                mma_tf32(o[mt][nt], ar[mt], bh);
                mma_tf32(o[mt][nt], ah[mt], br);
                mma_tf32(o[mt][nt], ah[mt], bh);
            }
        }
    }

#pragma unroll
    for (int mt = 0; mt < 2; mt++) {
        const int r0 = half * 32 + mt * 16 + g;
#pragma unroll
        for (int nt = 0; nt < 4; nt++) {
            const int col = h * HDIM + nt * 8 + 2 * t;
            const size_t e0 = ((size_t)b * N_TOK + r0)     * DIM_C + col;
            const size_t e1 = ((size_t)b * N_TOK + r0 + 8) * DIM_C + col;
            unsigned hi, res;
            bf16_split_pack(o[mt][nt][0], o[mt][nt][1], hi, res);
            ((unsigned*)g_aohi)[e0 >> 1]  = hi;
            ((unsigned*)g_aores)[e0 >> 1] = res;
            bf16_split_pack(o[mt][nt][2], o[mt][nt][3], hi, res);
            ((unsigned*)g_aohi)[e1 >> 1]  = hi;
            ((unsigned*)g_aores)[e1 >> 1] = res;
        }
    }
}

// ---------------------------------------------------------------------------
extern "C" void kernel_launch(void* const* d_in, const int* in_sizes, int n_in,
                              void* d_out, int out_size)
{
    const float* x      = (const float*)d_in[0];
    const float* wq     = (const float*)d_in[1];
    const float* bq     = (const float*)d_in[2];
    const float* wkv    = (const float*)d_in[3];
    const float* bkv    = (const float*)d_in[4];
    const float* wp     = (const float*)d_in[5];
    const float* bp     = (const float*)d_in[6];
    const float* rpb    = (const float*)d_in[7];
    const int*   relidx = (const int*)  d_in[8];
    float* out = (float*)d_out;

    float *qkv = nullptr, *bqkv = nullptr, *bias = nullptr;
    unsigned short *xhi, *xres, *aohi, *aores, *wthi, *wtres, *wpthi, *wptres;
    cudaGetSymbolAddress((void**)&qkv,    g_qkv);
    cudaGetSymbolAddress((void**)&bqkv,   g_bqkv);
    cudaGetSymbolAddress((void**)&bias,   g_bias);
    cudaGetSymbolAddress((void**)&xhi,    g_xhi);
    cudaGetSymbolAddress((void**)&xres,   g_xres);
    cudaGetSymbolAddress((void**)&aohi,   g_aohi);
    cudaGetSymbolAddress((void**)&aores,  g_aores);
    cudaGetSymbolAddress((void**)&wthi,   g_wthi);
    cudaGetSymbolAddress((void**)&wtres,  g_wtres);
    cudaGetSymbolAddress((void**)&wpthi,  g_wpthi);
    cudaGetSymbolAddress((void**)&wptres, g_wptres);

    cudaFuncSetAttribute(gemm_bf16x3, cudaFuncAttributeMaxDynamicSharedMemorySize, GEMM_SMEM);
    cudaFuncSetAttribute(attn_tc,     cudaFuncAttributeMaxDynamicSharedMemorySize, ATTN_SMEM);

    // 0a) split x into bf16 hi/res planes
    split_x<<<(M_ROWS * DIM_C / 2 + 255) / 256, 256>>>(x);
    // 0b) pack weights (q pre-scaled) + bias table
    pack_w<<<(QKV_LD * DIM_C + 255) / 256, 256>>>(wq, bq, wkv, bkv, wp, rpb, relidx);

    // 1) qkv = x @ wqkv + bqkv  — n-tile fastest for L2 A-reuse
    {
        dim3 grid(QKV_LD / 128, M_ROWS / 128);   // (6, 2048)
        gemm_bf16x3<<<grid, 256, GEMM_SMEM>>>(xhi, xres, wthi, wtres, bqkv, qkv,
                                              DIM_C, QKV_LD);
    }
    // 2) attention
    attn_tc<<<B_WIN, 512, ATTN_SMEM>>>(qkv, bias);

    // 3) out = ao @ wp + bp
    {
        dim3 grid(DIM_C / 128, M_ROWS / 128);    // (2, 2048)
        gemm_bf16x3<<<grid, 256, GEMM_SMEM>>>(aohi, aores, wpthi, wptres, bp, out,
                                              DIM_C, DIM_C);
    }
}

// round 10
// speedup vs baseline: 1.1813x; 1.1461x over previous
#include <cuda_runtime.h>
#include <cuda_bf16.h>
#include <cstdint>

// ---------------------------------------------------------------------------
// TotalAttention (Swin window attention), fused 3xBF16/3xTF32 pipeline:
//   0) pack_w: wq(*scale)|wkv -> transposed split planes [768][256]; wp ->
//      [256][256] planes; biases; bias table g_bias[h][n][m]
//   1) gemm_qkv: qkv = x @ wqkv + bqkv -> fp32 [M x 768]
//      (A = fp32 x, split to bf16 hi/res in-kernel; B planes cp.async; ldsm)
//   2) attn_fused: per window (512 thr): attention (3xTF32) -> O planes in
//      smem -> in-block out-proj (3xBF16, wp planes streamed) -> d_out fp32
// No tcgen05 (ptxas targets compute_103: tcgen05 unsupported) — mma.sync only.
// ---------------------------------------------------------------------------

#define B_WIN   4096
#define N_TOK   64
#define DIM_C   256
#define HEADS   8
#define HDIM    32
#define M_ROWS  (B_WIN * N_TOK)        // 262144
#define QKV_LD  768
#define SCALE_F 0.17677669529663687f   // 32^-0.5

__device__ float g_qkv[(size_t)M_ROWS * QKV_LD];            // 805 MB fp32
__device__ unsigned short g_wthi [QKV_LD * DIM_C];          // wqkv^T [768][256]
__device__ unsigned short g_wtres[QKV_LD * DIM_C];
__device__ unsigned short g_wpthi [DIM_C * DIM_C];          // wp^T [256][256]
__device__ unsigned short g_wptres[DIM_C * DIM_C];
__device__ float g_bqkv[QKV_LD];
__device__ float g_bias[HEADS * N_TOK * N_TOK];             // [h][n][m]

// ---------------------------------------------------------------------------
__device__ __forceinline__ void cp_async16(void* smem_dst, const void* gsrc) {
    unsigned saddr = (unsigned)__cvta_generic_to_shared(smem_dst);
    asm volatile("cp.async.cg.shared.global [%0], [%1], 16;\n"
                 :: "r"(saddr), "l"(gsrc));
}

__device__ __forceinline__ void ldsm_x4(unsigned* r, const void* p) {
    unsigned a = (unsigned)__cvta_generic_to_shared(p);
    asm volatile("ldmatrix.sync.aligned.m8n8.x4.shared.b16 {%0,%1,%2,%3}, [%4];"
                 : "=r"(r[0]), "=r"(r[1]), "=r"(r[2]), "=r"(r[3]) : "r"(a));
}

__device__ __forceinline__ void ldsm_x2(unsigned* r, const void* p) {
    unsigned a = (unsigned)__cvta_generic_to_shared(p);
    asm volatile("ldmatrix.sync.aligned.m8n8.x2.shared.b16 {%0,%1}, [%2];"
                 : "=r"(r[0]), "=r"(r[1]) : "r"(a));
}

__device__ __forceinline__ void mma_bf16(float* c, const unsigned* a, const unsigned* b) {
    asm volatile(
        "mma.sync.aligned.m16n8k16.row.col.f32.bf16.bf16.f32 "
        "{%0,%1,%2,%3}, {%4,%5,%6,%7}, {%8,%9}, {%0,%1,%2,%3};\n"
        : "+f"(c[0]), "+f"(c[1]), "+f"(c[2]), "+f"(c[3])
        : "r"(a[0]), "r"(a[1]), "r"(a[2]), "r"(a[3]),
          "r"(b[0]), "r"(b[1]));
}

__device__ __forceinline__ void mma_tf32(float* c, const unsigned* a, const unsigned* b) {
    asm volatile(
        "mma.sync.aligned.m16n8k8.row.col.f32.tf32.tf32.f32 "
        "{%0,%1,%2,%3}, {%4,%5,%6,%7}, {%8,%9}, {%0,%1,%2,%3};\n"
        : "+f"(c[0]), "+f"(c[1]), "+f"(c[2]), "+f"(c[3])
        : "r"(a[0]), "r"(a[1]), "r"(a[2]), "r"(a[3]),
          "r"(b[0]), "r"(b[1]));
}

__device__ __forceinline__ void tf32_split(float f, unsigned& hi, unsigned& res) {
    hi  = __float_as_uint(f) & 0xFFFFE000u;
    res = __float_as_uint(f - __uint_as_float(hi));
}

__device__ __forceinline__ void bf16_split(float f, unsigned short& hi, unsigned short& res) {
    __nv_bfloat16 h = __float2bfloat16_rn(f);
    float r = f - __bfloat162float(h);
    hi  = __bfloat16_as_ushort(h);
    res = __bfloat16_as_ushort(__float2bfloat16_rn(r));
}

__device__ __forceinline__ void bf16_split_pack(float a, float b, unsigned& hi, unsigned& res) {
    unsigned short ha, ra, hb, rb;
    bf16_split(a, ha, ra);
    bf16_split(b, hb, rb);
    hi  = (unsigned)ha | ((unsigned)hb << 16);
    res = (unsigned)ra | ((unsigned)rb << 16);
}

// ---------------------------------------------------------------------------
__global__ void pack_w(const float* __restrict__ wq, const float* __restrict__ bq,
                       const float* __restrict__ wkv, const float* __restrict__ bkv,
                       const float* __restrict__ wp,
                       const float* __restrict__ rpb, const int* __restrict__ relidx)
{
    int i = blockIdx.x * blockDim.x + threadIdx.x;
    if (i < QKV_LD * DIM_C) {                 // wqkv^T: [n=768][k=256]
        int n = i / DIM_C, k = i % DIM_C;
        float v = (n < DIM_C) ? wq[k * DIM_C + n] * SCALE_F
                              : wkv[k * 512 + (n - DIM_C)];
        bf16_split(v, g_wthi[i], g_wtres[i]);
    }
    if (i < DIM_C * DIM_C) {                  // wp^T: [n=256][k=256]
        int n = i / DIM_C, k = i % DIM_C;
        bf16_split(wp[k * DIM_C + n], g_wpthi[i], g_wptres[i]);
    }
    if (i < QKV_LD) g_bqkv[i] = (i < DIM_C) ? bq[i] * SCALE_F : bkv[i - DIM_C];
    if (i < HEADS * N_TOK * N_TOK) {
        int h = i >> 12, nm = i & 4095;
        g_bias[i] = rpb[relidx[nm] * HEADS + h];
    }
}

// ---------------------------------------------------------------------------
// qkv GEMM (3xBF16, ldsm, in-kernel A split):
//   C[m0..+128, n0..+128] = x @ W^T + bias.  K=256, BK=32 (8 kt).
// A: fp32 x loaded to regs (double-buffered), split -> bf16 planes in smem.
// B: pre-split planes via cp.async (double-buffered).
// Smem shorts layout: A bufs [2][hi 5120 | res 5120], B bufs same after.
// ---------------------------------------------------------------------------
#define TPAD 40
#define APLANE (128 * TPAD)             // 5120 shorts
#define ABUF   (2 * APLANE)             // hi+res, 10240 shorts
#define BBASE  (2 * ABUF)               // 20480 shorts
#define GEMM_SMEM (4 * ABUF * 2)        // 81920 bytes

__global__ __launch_bounds__(256, 2)
void gemm_qkv(const float* __restrict__ X,
              const unsigned short* __restrict__ Bhi_g,
              const unsigned short* __restrict__ Bres_g,
              const float* __restrict__ bias, float* __restrict__ C)
{
    extern __shared__ __align__(16) unsigned short smu[];

    const int tid  = threadIdx.x;
    const int warp = tid >> 5, lane = tid & 31;
    const int wm = warp >> 2, wn = warp & 3;
    const int g  = lane >> 2, t  = lane & 3;
    const size_t n0 = (size_t)blockIdx.x * 128;   // n fastest (L2 x-reuse)
    const size_t m0 = (size_t)blockIdx.y * 128;

    // B cp.async mapping: 512 16B-chunks per plane, 2 per thread per plane
    const int c0   = tid * 2;
    const int brow0 = c0 >> 2, bcc0 = (c0 & 3) * 8;
    const int brow1 = (c0 + 1) >> 2, bcc1 = ((c0 + 1) & 3) * 8;

    // A fp32 mapping: 1024 float4 chunks, 4 per thread (coalesced)
    int arow[4], acc_[4];
#pragma unroll
    for (int j = 0; j < 4; j++) {
        const int c = tid + 256 * j;
        arow[j] = c >> 3;
        acc_[j] = (c & 7) * 4;
    }

    // ldmatrix lane mapping
    const int la_row = lane & 15;
    const int la_col = (lane >> 4) * 8;
    const int lb_row = lane & 7;
    const int lb_col = ((lane >> 3) & 1) * 8;

    float acc[4][4][4];
#pragma unroll
    for (int mt = 0; mt < 4; mt++)
#pragma unroll
        for (int nt = 0; nt < 4; nt++)
#pragma unroll
            for (int r = 0; r < 4; r++) acc[mt][nt][r] = 0.0f;

    auto issue_B = [&](int kt, int buf) {
        unsigned short* bh = smu + BBASE + buf * ABUF;
        unsigned short* br = bh + APLANE;
        const int ko = kt * 32;
        cp_async16(&bh[brow0 * TPAD + bcc0], Bhi_g  + (n0 + brow0) * 256 + ko + bcc0);
        cp_async16(&bh[brow1 * TPAD + bcc1], Bhi_g  + (n0 + brow1) * 256 + ko + bcc1);
        cp_async16(&br[brow0 * TPAD + bcc0], Bres_g + (n0 + brow0) * 256 + ko + bcc0);
        cp_async16(&br[brow1 * TPAD + bcc1], Bres_g + (n0 + brow1) * 256 + ko + bcc1);
        asm volatile("cp.async.commit_group;\n");
    };

    auto load_A = [&](int kt, float4* regs) {
        const int ko = kt * 32;
#pragma unroll
        for (int j = 0; j < 4; j++)
            regs[j] = *(const float4*)(X + (m0 + arow[j]) * 256 + ko + acc_[j]);
    };

    float4 aReg[4];
    load_A(0, aReg);
    issue_B(0, 0);

    for (int kt = 0; kt < 8; ++kt) {
        asm volatile("cp.async.wait_group 0;\n" ::: "memory");

        // STS: split A regs -> planes of buffer kt&1 (other buffer is being
        // computed-from nowhere: last consumed two iterations ago)
        {
            unsigned short* ah = smu + (kt & 1) * ABUF;
            unsigned short* ar = ah + APLANE;
#pragma unroll
            for (int j = 0; j < 4; j++) {
                unsigned h0, r0w, h1, r1w;
                bf16_split_pack(aReg[j].x, aReg[j].y, h0, r0w);
                bf16_split_pack(aReg[j].z, aReg[j].w, h1, r1w);
                const int off = arow[j] * TPAD + acc_[j];
                *(unsigned long long*)&ah[off] =
                    (unsigned long long)h0 | ((unsigned long long)h1 << 32);
                *(unsigned long long*)&ar[off] =
                    (unsigned long long)r0w | ((unsigned long long)r1w << 32);
            }
        }
        __syncthreads();   // A(kt) STS + B(kt) cp.async visible to all

        if (kt + 1 < 8) {
            load_A(kt + 1, aReg);
            issue_B(kt + 1, (kt + 1) & 1);
        }

        const unsigned short* As_hi  = smu + (kt & 1) * ABUF;
        const unsigned short* As_res = As_hi + APLANE;
        const unsigned short* Bs_hi  = smu + BBASE + (kt & 1) * ABUF;
        const unsigned short* Bs_res = Bs_hi + APLANE;

#pragma unroll
        for (int ks = 0; ks < 2; ++ks) {
            const int ck = ks * 16;
            unsigned bh[4][2], br[4][2];
#pragma unroll
            for (int nt = 0; nt < 4; nt++) {
                const int boff = (wn * 32 + nt * 8 + lb_row) * TPAD + ck + lb_col;
                ldsm_x2(bh[nt], Bs_hi  + boff);
                ldsm_x2(br[nt], Bs_res + boff);
            }
#pragma unroll
            for (int mt = 0; mt < 4; mt++) {
                const int aoff = (wm * 64 + mt * 16 + la_row) * TPAD + ck + la_col;
                unsigned ah[4], ar[4];
                ldsm_x4(ah, As_hi  + aoff);
                ldsm_x4(ar, As_res + aoff);
#pragma unroll
                for (int nt = 0; nt < 4; nt++) {
                    mma_bf16(acc[mt][nt], ar, bh[nt]);
                    mma_bf16(acc[mt][nt], ah, br[nt]);
                    mma_bf16(acc[mt][nt], ah, bh[nt]);
                }
            }
        }
        __syncthreads();   // buffer consumed before next-iter STS/cp.async
    }

#pragma unroll
    for (int mt = 0; mt < 4; mt++) {
        const size_t r0 = m0 + wm * 64 + mt * 16 + g;
#pragma unroll
        for (int nt = 0; nt < 4; nt++) {
            const size_t col = n0 + wn * 32 + nt * 8 + 2 * t;
            const float b0 = bias[col], b1 = bias[col + 1];
            float* cp0 = C + r0 * QKV_LD + col;
            float* cp1 = C + (r0 + 8) * QKV_LD + col;
            *(float2*)cp0 = make_float2(acc[mt][nt][0] + b0, acc[mt][nt][1] + b1);
            *(float2*)cp1 = make_float2(acc[mt][nt][2] + b0, acc[mt][nt][3] + b1);
        }
    }
}

// ---------------------------------------------------------------------------
// Attention + fused out-proj. Block = window, 512 threads.
// Phase 1 (attention, as r8): 2 warps/head; Q/K/V fp32 smem via cp.async;
//   3xTF32 QK^T + bias + softmax + PV. O stays in registers.
// Phase 2 (out-proj): O -> smem bf16 hi/res planes AO[64][256] (stride 264);
//   out = AO @ wp^T + bp via 3xBF16 mma, wp planes streamed (double-buffered
//   cp.async), 16 warps in 2x8 grid (warp tile 32x32). Smem reused (aliases
//   the dead head regions after a full-block barrier).
// ---------------------------------------------------------------------------
#define QS_STRIDE 36
#define KS_STRIDE 36
#define VS_STRIDE 40
#define PS_STRIDE 68
#define HEAD_FLOATS (64 * QS_STRIDE + 64 * KS_STRIDE + 64 * VS_STRIDE)  // 7168
#define ATTN_SMEM (8 * HEAD_FLOATS * 4)   // 229376 bytes

#define AO_STRIDE 264                     // shorts
#define AO_PLANE  (64 * AO_STRIDE)        // 16896 shorts
#define WP_PLANE  (256 * TPAD)            // 10240 shorts per plane
#define WP_BUF    (2 * WP_PLANE)          // hi+res per buffer

__global__ __launch_bounds__(512, 1)
void attn_fused(const float* __restrict__ qkv,
                const float* __restrict__ bias,
                const unsigned short* __restrict__ WPhi,
                const unsigned short* __restrict__ WPres,
                const float* __restrict__ bp,
                float* __restrict__ out)
{
    extern __shared__ float sm[];
    const int b    = blockIdx.x;
    const int tid  = threadIdx.x;
    const int warp = tid >> 5;
    const int lane = tid & 31;
    const int h    = warp >> 1;
    const int half = warp & 1;
    const int g = lane >> 2, t = lane & 3;

    float* QS = sm + h * HEAD_FLOATS;
    float* KS = QS + 64 * QS_STRIDE;
    float* VS = KS + 64 * KS_STRIDE;
    float* PS = QS;

    // ---- phase-1 load via cp.async ----
    const size_t base = (size_t)b * N_TOK * QKV_LD + h * HDIM;
    for (int i = half * 32 + lane; i < 512; i += 64) {
        const int row = i >> 3;
        const int c4  = (i & 7) << 2;
        const float* rp = qkv + base + (size_t)row * QKV_LD + c4;
        cp_async16(&QS[row * QS_STRIDE + c4], rp);
        cp_async16(&KS[row * KS_STRIDE + c4], rp + 256);
        cp_async16(&VS[row * VS_STRIDE + c4], rp + 512);
    }
    asm volatile("cp.async.commit_group;\n");
    asm volatile("cp.async.wait_group 0;\n" ::: "memory");
    __syncthreads();

    // ---- S = Q @ K^T (3xTF32) ----
    float s_[2][8][4];
#pragma unroll
    for (int mt = 0; mt < 2; mt++)
#pragma unroll
        for (int nt = 0; nt < 8; nt++)
#pragma unroll
            for (int r = 0; r < 4; r++) s_[mt][nt][r] = 0.0f;

#pragma unroll
    for (int ks = 0; ks < 4; ++ks) {
        const int ck = ks * 8;
        unsigned ah[2][4], ar[2][4];
#pragma unroll
        for (int mt = 0; mt < 2; mt++) {
            const float* p = QS + (half * 32 + mt * 16 + g) * QS_STRIDE + ck + t;
            tf32_split(p[0],                 ah[mt][0], ar[mt][0]);
            tf32_split(p[8 * QS_STRIDE],     ah[mt][1], ar[mt][1]);
            tf32_split(p[4],                 ah[mt][2], ar[mt][2]);
            tf32_split(p[8 * QS_STRIDE + 4], ah[mt][3], ar[mt][3]);
        }
#pragma unroll
        for (int nt = 0; nt < 8; nt++) {
            const float* p = KS + (nt * 8 + g) * KS_STRIDE + ck + t;
            unsigned bh[2], br[2];
            tf32_split(p[0], bh[0], br[0]);
            tf32_split(p[4], bh[1], br[1]);
#pragma unroll
            for (int mt = 0; mt < 2; mt++) {
                mma_tf32(s_[mt][nt], ar[mt], bh);
                mma_tf32(s_[mt][nt], ah[mt], br);
                mma_tf32(s_[mt][nt], ah[mt], bh);
            }
        }
    }

    // ---- bias ----
    const float* bh_tab = bias + h * (N_TOK * N_TOK);
#pragma unroll
    for (int mt = 0; mt < 2; mt++) {
        const int r0 = half * 32 + mt * 16 + g;
#pragma unroll
        for (int nt = 0; nt < 8; nt++) {
            const int c = nt * 8 + 2 * t;
            float2 b0 = *(const float2*)&bh_tab[r0 * 64 + c];
            float2 b1 = *(const float2*)&bh_tab[(r0 + 8) * 64 + c];
            s_[mt][nt][0] += b0.x;  s_[mt][nt][1] += b0.y;
            s_[mt][nt][2] += b1.x;  s_[mt][nt][3] += b1.y;
        }
    }

    // ---- softmax ----
#pragma unroll
    for (int mt = 0; mt < 2; mt++) {
        float m0 = -1e30f, m1 = -1e30f;
#pragma unroll
        for (int nt = 0; nt < 8; nt++) {
            m0 = fmaxf(m0, fmaxf(s_[mt][nt][0], s_[mt][nt][1]));
            m1 = fmaxf(m1, fmaxf(s_[mt][nt][2], s_[mt][nt][3]));
        }
        m0 = fmaxf(m0, __shfl_xor_sync(0xffffffffu, m0, 1));
        m0 = fmaxf(m0, __shfl_xor_sync(0xffffffffu, m0, 2));
        m1 = fmaxf(m1, __shfl_xor_sync(0xffffffffu, m1, 1));
        m1 = fmaxf(m1, __shfl_xor_sync(0xffffffffu, m1, 2));
        float s0 = 0.0f, s1 = 0.0f;
#pragma unroll
        for (int nt = 0; nt < 8; nt++) {
            s_[mt][nt][0] = __expf(s_[mt][nt][0] - m0);
            s_[mt][nt][1] = __expf(s_[mt][nt][1] - m0);
            s_[mt][nt][2] = __expf(s_[mt][nt][2] - m1);
            s_[mt][nt][3] = __expf(s_[mt][nt][3] - m1);
            s0 += s_[mt][nt][0] + s_[mt][nt][1];
            s1 += s_[mt][nt][2] + s_[mt][nt][3];
        }
        s0 += __shfl_xor_sync(0xffffffffu, s0, 1);
        s0 += __shfl_xor_sync(0xffffffffu, s0, 2);
        s1 += __shfl_xor_sync(0xffffffffu, s1, 1);
        s1 += __shfl_xor_sync(0xffffffffu, s1, 2);
        const float i0 = __frcp_rn(s0), i1 = __frcp_rn(s1);
#pragma unroll
        for (int nt = 0; nt < 8; nt++) {
            s_[mt][nt][0] *= i0;  s_[mt][nt][1] *= i0;
            s_[mt][nt][2] *= i1;  s_[mt][nt][3] *= i1;
        }
    }

    asm volatile("bar.sync %0, %1;" :: "r"(1 + h), "r"(64) : "memory");

#pragma unroll
    for (int mt = 0; mt < 2; mt++) {
        const int r0 = half * 32 + mt * 16 + g;
#pragma unroll
        for (int nt = 0; nt < 8; nt++) {
            const int c = nt * 8 + 2 * t;
            *(float2*)&PS[r0 * PS_STRIDE + c]       = make_float2(s_[mt][nt][0], s_[mt][nt][1]);
            *(float2*)&PS[(r0 + 8) * PS_STRIDE + c] = make_float2(s_[mt][nt][2], s_[mt][nt][3]);
        }
    }
    asm volatile("bar.sync %0, %1;" :: "r"(1 + h), "r"(64) : "memory");

    // ---- O = P @ V (3xTF32) ----
    float o[2][4][4];
#pragma unroll
    for (int mt = 0; mt < 2; mt++)
#pragma unroll
        for (int nt = 0; nt < 4; nt++)
#pragma unroll
            for (int r = 0; r < 4; r++) o[mt][nt][r] = 0.0f;

#pragma unroll
    for (int ks = 0; ks < 8; ++ks) {
        const int ck = ks * 8;
        unsigned ah[2][4], ar[2][4];
#pragma unroll
        for (int mt = 0; mt < 2; mt++) {
            const float* p = PS + (half * 32 + mt * 16 + g) * PS_STRIDE + ck + t;
            tf32_split(p[0],                 ah[mt][0], ar[mt][0]);
            tf32_split(p[8 * PS_STRIDE],     ah[mt][1], ar[mt][1]);
            tf32_split(p[4],                 ah[mt][2], ar[mt][2]);
            tf32_split(p[8 * PS_STRIDE + 4], ah[mt][3], ar[mt][3]);
        }
#pragma unroll
        for (int nt = 0; nt < 4; nt++) {
            const float* p = VS + (ck + t) * VS_STRIDE + nt * 8 + g;
            unsigned bh[2], br[2];
            tf32_split(p[0],             bh[0], br[0]);
            tf32_split(p[4 * VS_STRIDE], bh[1], br[1]);
#pragma unroll
            for (int mt = 0; mt < 2; mt++) {
                mma_tf32(o[mt][nt], ar[mt], bh);
                mma_tf32(o[mt][nt], ah[mt], br);
                mma_tf32(o[mt][nt], ah[mt], bh);
            }
        }
    }

    // ============ phase 2: fused out-proj ============
    __syncthreads();   // ALL heads done reading Q/K/V/P smem

    unsigned short* AOhi  = (unsigned short*)sm;
    unsigned short* AOres = AOhi + AO_PLANE;
    unsigned short* WPbuf = AOres + AO_PLANE;   // 2 x WP_BUF shorts

    // write O as bf16 hi/res planes
#pragma unroll
    for (int mt = 0; mt < 2; mt++) {
        const int r0 = half * 32 + mt * 16 + g;
#pragma unroll
        for (int nt = 0; nt < 4; nt++) {
            const int col = h * HDIM + nt * 8 + 2 * t;
            unsigned hi, res;
            bf16_split_pack(o[mt][nt][0], o[mt][nt][1], hi, res);
            *(unsigned*)&AOhi [r0 * AO_STRIDE + col] = hi;
            *(unsigned*)&AOres[r0 * AO_STRIDE + col] = res;
            bf16_split_pack(o[mt][nt][2], o[mt][nt][3], hi, res);
            *(unsigned*)&AOhi [(r0 + 8) * AO_STRIDE + col] = hi;
            *(unsigned*)&AOres[(r0 + 8) * AO_STRIDE + col] = res;
        }
    }

    // wp slice fill: kt slice is [256 n][32 k]; 1024 chunks16B per plane
    auto issue_wp = [&](int kt, int buf) {
        unsigned short* bh = WPbuf + buf * WP_BUF;
        unsigned short* br = bh + WP_PLANE;
        const int ko = kt * 32;
        for (int j = tid; j < 1024; j += 512) {
            const int row = j >> 2, ch = (j & 3) * 8;
            cp_async16(&bh[row * TPAD + ch], WPhi  + row * 256 + ko + ch);
            cp_async16(&br[row * TPAD + ch], WPres + row * 256 + ko + ch);
        }
        asm volatile("cp.async.commit_group;\n");
    };

    issue_wp(0, 0);
    __syncthreads();   // AO visible to all

    // warp grid 2(m) x 8(n); warp tile 32m x 32n
    const int wm2 = warp >> 3;          // 0..1
    const int wn2 = warp & 7;           // 0..7
    const int la_row = lane & 15;
    const int la_col = (lane >> 4) * 8;
    const int lb_row = lane & 7;
    const int lb_col = ((lane >> 3) & 1) * 8;

    float oc[2][4][4];
#pragma unroll
    for (int mt = 0; mt < 2; mt++)
#pragma unroll
        for (int nt = 0; nt < 4; nt++)
#pragma unroll
            for (int r = 0; r < 4; r++) oc[mt][nt][r] = 0.0f;

    for (int kt = 0; kt < 8; ++kt) {
        asm volatile("cp.async.wait_group 0;\n" ::: "memory");
        __syncthreads();
        if (kt + 1 < 8) issue_wp(kt + 1, (kt + 1) & 1);

        const unsigned short* Bh = WPbuf + (kt & 1) * WP_BUF;
        const unsigned short* Br = Bh + WP_PLANE;

#pragma unroll
        for (int ks = 0; ks < 2; ++ks) {
            const int ck = kt * 32 + ks * 16;   // A col
            const int bk = ks * 16;             // B col
            unsigned bh[4][2], br[4][2];
#pragma unroll
            for (int nt = 0; nt < 4; nt++) {
                const int boff = (wn2 * 32 + nt * 8 + lb_row) * TPAD + bk + lb_col;
                ldsm_x2(bh[nt], Bh + boff);
                ldsm_x2(br[nt], Br + boff);
            }
#pragma unroll
            for (int mt = 0; mt < 2; mt++) {
                const int aoff = (wm2 * 32 + mt * 16 + la_row) * AO_STRIDE + ck + la_col;
                unsigned ah[4], ar[4];
                ldsm_x4(ah, AOhi  + aoff);
                ldsm_x4(ar, AOres + aoff);
#pragma unroll
                for (int nt = 0; nt < 4; nt++) {
                    mma_bf16(oc[mt][nt], ar, bh[nt]);
                    mma_bf16(oc[mt][nt], ah, br[nt]);
                    mma_bf16(oc[mt][nt], ah, bh[nt]);
                }
            }
        }
        __syncthreads();
    }

    // epilogue: bias + store
#pragma unroll
    for (int mt = 0; mt < 2; mt++) {
        const int r0 = wm2 * 32 + mt * 16 + g;
#pragma unroll
        for (int nt = 0; nt < 4; nt++) {
            const int col = wn2 * 32 + nt * 8 + 2 * t;
            const float b0 = bp[col], b1 = bp[col + 1];
            float* op0 = out + ((size_t)b * N_TOK + r0)     * DIM_C + col;
            float* op1 = out + ((size_t)b * N_TOK + r0 + 8) * DIM_C + col;
            *(float2*)op0 = make_float2(oc[mt][nt][0] + b0, oc[mt][nt][1] + b1);
            *(float2*)op1 = make_float2(oc[mt][nt][2] + b0, oc[mt][nt][3] + b1);
        }
    }
}

// ---------------------------------------------------------------------------
extern "C" void kernel_launch(void* const* d_in, const int* in_sizes, int n_in,
                              void* d_out, int out_size)
{
    const float* x      = (const float*)d_in[0];
    const float* wq     = (const float*)d_in[1];
    const float* bq     = (const float*)d_in[2];
    const float* wkv    = (const float*)d_in[3];
    const float* bkv    = (const float*)d_in[4];
    const float* wp     = (const float*)d_in[5];
    const float* bp     = (const float*)d_in[6];
    const float* rpb    = (const float*)d_in[7];
    const int*   relidx = (const int*)  d_in[8];
    float* out = (float*)d_out;

    float *qkv = nullptr, *bqkv = nullptr, *bias = nullptr;
    unsigned short *wthi, *wtres, *wpthi, *wptres;
    cudaGetSymbolAddress((void**)&qkv,    g_qkv);
    cudaGetSymbolAddress((void**)&bqkv,   g_bqkv);
    cudaGetSymbolAddress((void**)&bias,   g_bias);
    cudaGetSymbolAddress((void**)&wthi,   g_wthi);
    cudaGetSymbolAddress((void**)&wtres,  g_wtres);
    cudaGetSymbolAddress((void**)&wpthi,  g_wpthi);
    cudaGetSymbolAddress((void**)&wptres, g_wptres);

    cudaFuncSetAttribute(gemm_qkv,   cudaFuncAttributeMaxDynamicSharedMemorySize, GEMM_SMEM);
    cudaFuncSetAttribute(attn_fused, cudaFuncAttributeMaxDynamicSharedMemorySize, ATTN_SMEM);

    // 0) pack weights (q pre-scaled) + bias table
    pack_w<<<(QKV_LD * DIM_C + 255) / 256, 256>>>(wq, bq, wkv, bkv, wp, rpb, relidx);

    // 1) qkv = x @ wqkv + bqkv  (in-kernel split; n-tile fastest for L2 reuse)
    {
        dim3 grid(QKV_LD / 128, M_ROWS / 128);   // (6, 2048)
        gemm_qkv<<<grid, 256, GEMM_SMEM>>>(x, wthi, wtres, bqkv, qkv);
    }
    // 2) attention + fused out-proj
    attn_fused<<<B_WIN, 512, ATTN_SMEM>>>(qkv, bias, wpthi, wptres, bp, out);
}